// round 1
// baseline (speedup 1.0000x reference)
#include <cuda_runtime.h>
#include <cuda_bf16.h>

// Gridworld env step, fused: move logic + consume + 11x11 window gather +
// 6-channel observation build. new_grids is never materialized: the only
// modified cell is the window center, overridden in-register.
//
// Inputs (metadata order):
//   0 grids              (N, 64, 64) f32
//   1 agent_energy       (N,)        f32
//   2 interestingness_lut(5,)        f32
//   3 agent_x            (N,)        i32
//   4 agent_y            (N,)        i32
//   5 agent_steps        (N,)        i32   (unused)
//   6 actions            (N,)        i32
//   7 action_deltas      (9, 2)      i32
// Output: obs (N, 6, 11, 11) f32

#define HW   64
#define VIEW 11
#define RAD  5
#define CELLS (VIEW * VIEW)   // 121
#define OBS_PER_ENV (6 * CELLS) // 726

__global__ __launch_bounds__(128, 16)
void env_step_kernel(const float* __restrict__ grids,
                     const float* __restrict__ energy_in,
                     const float* __restrict__ lut,
                     const int*   __restrict__ agent_x,
                     const int*   __restrict__ agent_y,
                     const int*   __restrict__ actions,
                     const int*   __restrict__ deltas,
                     float*       __restrict__ out)
{
    const int env = blockIdx.x;
    const int t   = threadIdx.x;

    const float* __restrict__ g = grids + (size_t)env * (HW * HW);

    // ---- per-env move logic (redundant across threads; loads broadcast) ----
    const int a  = __ldg(actions + env);
    const int dy = __ldg(deltas + 2 * a);
    const int dx = __ldg(deltas + 2 * a + 1);
    const int y0 = __ldg(agent_y + env);
    const int x0 = __ldg(agent_x + env);

    int ny = min(max(y0 + dy, 0), HW - 1);
    int nx = min(max(x0 + dx, 0), HW - 1);

    const float tgt = __ldg(g + ny * HW + nx);
    if (tgt == 1.0f) { ny = y0; nx = x0; }   // wall: stay

    const float cell   = __ldg(g + ny * HW + nx);
    const bool  food   = (cell == 2.0f);
    const bool  poison = (cell == 3.0f);
    const bool  consumed = food | poison;
    const float reward = (food ? 10.0f : 0.0f) - (poison ? 10.0f : 0.0f);
    const float energy = __ldg(energy_in + env) - 1.0f + reward;

    // lut is 5 floats, L2-hot; preload the 4 reachable entries into registers
    const float l0 = __ldg(lut + 0);
    const float l1 = __ldg(lut + 1);
    const float l2 = __ldg(lut + 2);
    const float l3 = __ldg(lut + 3);

    if (t < CELLS) {
        const int wy = t / VIEW - RAD;
        const int wx = t % VIEW - RAD;
        const int gy = ny + wy;
        const int gx = nx + wx;

        float w;
        if ((unsigned)gy < (unsigned)HW && (unsigned)gx < (unsigned)HW)
            w = __ldg(g + gy * HW + gx);
        else
            w = 1.0f;                          // pad with WALL

        // the landed (center) cell was consumed -> EMPTY in new_grids
        if (consumed && wy == 0 && wx == 0)
            w = 0.0f;

        const int   wi = (int)w;               // 0..3
        const float lv = (wi == 0) ? l0 : (wi == 1) ? l1 : (wi == 2) ? l2 : l3;

        float* __restrict__ o = out + (size_t)env * OBS_PER_ENV + t;
        o[0 * CELLS] = (w == 2.0f) ? 1.0f : 0.0f;   // food mask
        o[1 * CELLS] = (w == 3.0f) ? 1.0f : 0.0f;   // poison mask
        o[2 * CELLS] = (w == 1.0f) ? 1.0f : 0.0f;   // wall mask
        o[3 * CELLS] = lv;                          // interestingness
        o[4 * CELLS] = w;                           // raw window
        o[5 * CELLS] = energy;                      // energy broadcast
    }
}

extern "C" void kernel_launch(void* const* d_in, const int* in_sizes, int n_in,
                              void* d_out, int out_size)
{
    const float* grids   = (const float*)d_in[0];
    const float* energy  = (const float*)d_in[1];
    const float* lut     = (const float*)d_in[2];
    const int*   ax      = (const int*)  d_in[3];
    const int*   ay      = (const int*)  d_in[4];
    // d_in[5] agent_steps unused
    const int*   actions = (const int*)  d_in[6];
    const int*   deltas  = (const int*)  d_in[7];
    float*       out     = (float*)      d_out;

    const int n_envs = in_sizes[1];   // agent_energy element count

    env_step_kernel<<<n_envs, 128>>>(grids, energy, lut, ax, ay, actions, deltas, out);
}

// round 2
// speedup vs baseline: 1.1429x; 1.1429x over previous
#include <cuda_runtime.h>
#include <cuda_bf16.h>

// Gridworld env step, warp-per-env version.
// Each warp owns one env: all lanes redundantly run the (tiny) move logic with
// the two candidate-cell loads issued IN PARALLEL (tgt + stay), then each lane
// gathers 4 window cells (lane, lane+32, lane+64, lane+96 < 121) giving MLP=4
// per thread and 64 independent env chains per SM.
//
// Inputs (metadata order):
//   0 grids (N,64,64) f32 | 1 energy (N,) f32 | 2 lut (5,) f32
//   3 agent_x (N,) i32 | 4 agent_y (N,) i32 | 5 agent_steps (unused)
//   6 actions (N,) i32 | 7 action_deltas (9,2) i32
// Output: obs (N, 6, 11, 11) f32

#define HW   64
#define VIEW 11
#define RAD  5
#define CELLS 121            // 11*11
#define OBS_PER_ENV 726      // 6*121
#define ENVS_PER_BLOCK 8     // 256 threads / 32

__global__ __launch_bounds__(256, 8)
void env_step_kernel(const float* __restrict__ grids,
                     const float* __restrict__ energy_in,
                     const float* __restrict__ lut,
                     const int*   __restrict__ agent_x,
                     const int*   __restrict__ agent_y,
                     const int*   __restrict__ actions,
                     const int*   __restrict__ deltas,
                     float*       __restrict__ out,
                     int n_envs)
{
    const int env  = blockIdx.x * ENVS_PER_BLOCK + (threadIdx.x >> 5);
    const int lane = threadIdx.x & 31;
    if (env >= n_envs) return;

    const float* __restrict__ g = grids + (size_t)env * (HW * HW);

    // ---- per-env move logic (redundant per lane; loads broadcast) ----
    const int a  = __ldg(actions + env);
    const int dy = __ldg(deltas + 2 * a);
    const int dx = __ldg(deltas + 2 * a + 1);
    const int y0 = __ldg(agent_y + env);
    const int x0 = __ldg(agent_x + env);

    const int nyc = min(max(y0 + dy, 0), HW - 1);
    const int nxc = min(max(x0 + dx, 0), HW - 1);

    // two INDEPENDENT loads — removes one serial memory round trip
    const float tgt  = __ldg(g + nyc * HW + nxc);
    const float stay = __ldg(g + y0  * HW + x0);

    const bool blocked = (tgt == 1.0f);
    const int  ny = blocked ? y0 : nyc;
    const int  nx = blocked ? x0 : nxc;
    const float cell = blocked ? stay : tgt;

    const bool  food     = (cell == 2.0f);
    const bool  poison   = (cell == 3.0f);
    const bool  consumed = food | poison;
    const float reward   = (food ? 10.0f : 0.0f) - (poison ? 10.0f : 0.0f);
    const float energy   = __ldg(energy_in + env) - 1.0f + reward;

    // lut: 4 reachable entries, independent L2-hot loads
    const float l0 = __ldg(lut + 0);
    const float l1 = __ldg(lut + 1);
    const float l2 = __ldg(lut + 2);
    const float l3 = __ldg(lut + 3);

    // ---- window gather: 4 cells per lane, all loads independent ----
    float w[4];
    #pragma unroll
    for (int j = 0; j < 4; j++) {
        const int c = lane + 32 * j;          // cell index 0..127
        const int wy = c / VIEW - RAD;        // c<121 valid
        const int wx = c % VIEW - RAD;
        const int gy = ny + wy;
        const int gx = nx + wx;
        float v = 1.0f;                        // WALL padding
        if (c < CELLS && (unsigned)gy < (unsigned)HW && (unsigned)gx < (unsigned)HW)
            v = __ldg(g + gy * HW + gx);
        // center cell consumed -> EMPTY
        if (consumed && c == 60)               // wy==0 && wx==0 <=> c==5*11+5
            v = 0.0f;
        w[j] = v;
    }

    float* __restrict__ o = out + (size_t)env * OBS_PER_ENV;
    #pragma unroll
    for (int j = 0; j < 4; j++) {
        const int c = lane + 32 * j;
        if (c < CELLS) {
            const float v  = w[j];
            const int   vi = (int)v;
            const float lv = (vi == 0) ? l0 : (vi == 1) ? l1 : (vi == 2) ? l2 : l3;
            o[0 * CELLS + c] = (v == 2.0f) ? 1.0f : 0.0f;
            o[1 * CELLS + c] = (v == 3.0f) ? 1.0f : 0.0f;
            o[2 * CELLS + c] = (v == 1.0f) ? 1.0f : 0.0f;
            o[3 * CELLS + c] = lv;
            o[4 * CELLS + c] = v;
            o[5 * CELLS + c] = energy;
        }
    }
}

extern "C" void kernel_launch(void* const* d_in, const int* in_sizes, int n_in,
                              void* d_out, int out_size)
{
    const float* grids   = (const float*)d_in[0];
    const float* energy  = (const float*)d_in[1];
    const float* lut     = (const float*)d_in[2];
    const int*   ax      = (const int*)  d_in[3];
    const int*   ay      = (const int*)  d_in[4];
    // d_in[5] agent_steps unused
    const int*   actions = (const int*)  d_in[6];
    const int*   deltas  = (const int*)  d_in[7];
    float*       out     = (float*)      d_out;

    const int n_envs = in_sizes[1];
    const int blocks = (n_envs + ENVS_PER_BLOCK - 1) / ENVS_PER_BLOCK;

    env_step_kernel<<<blocks, 256>>>(grids, energy, lut, ax, ay, actions, deltas, out, n_envs);
}

// round 3
// speedup vs baseline: 1.1462x; 1.0029x over previous
#include <cuda_runtime.h>
#include <cuda_bf16.h>

// Gridworld env step, warp-per-env, 2-memory-round critical path.
// Round 1: per-env scalars + full deltas table (parallel loads).
// Round 2: BOTH candidate 11x11 windows gathered in parallel (blocked-move
// resolution happens after, via shuffle of the window centers).
//
// Inputs (metadata order):
//   0 grids (N,64,64) f32 | 1 energy (N,) f32 | 2 lut (5,) f32
//   3 agent_x (N,) i32 | 4 agent_y (N,) i32 | 5 agent_steps (unused)
//   6 actions (N,) i32 | 7 action_deltas (9,2) i32
// Output: obs (N, 6, 11, 11) f32

#define HW   64
#define VIEW 11
#define RAD  5
#define CELLS 121            // 11*11
#define OBS_PER_ENV 726      // 6*121
#define ENVS_PER_BLOCK 8     // 256 threads / 32

__global__ __launch_bounds__(256, 6)
void env_step_kernel(const float* __restrict__ grids,
                     const float* __restrict__ energy_in,
                     const float* __restrict__ lut,
                     const int*   __restrict__ agent_x,
                     const int*   __restrict__ agent_y,
                     const int*   __restrict__ actions,
                     const int*   __restrict__ deltas,
                     float*       __restrict__ out,
                     int n_envs)
{
    const int env  = blockIdx.x * ENVS_PER_BLOCK + (threadIdx.x >> 5);
    const int lane = threadIdx.x & 31;
    if (env >= n_envs) return;

    const float* __restrict__ g = grids + (size_t)env * (HW * HW);

    // ---- ROUND 1: all independent loads issued together ----
    const int   a    = __ldg(actions + env);
    const int   y0   = __ldg(agent_y + env);
    const int   x0   = __ldg(agent_x + env);
    const float en0  = __ldg(energy_in + env);
    const int   dval = (lane < 18) ? __ldg(deltas + lane) : 0;  // whole table
    const float l0 = __ldg(lut + 0);
    const float l1 = __ldg(lut + 1);
    const float l2 = __ldg(lut + 2);
    const float l3 = __ldg(lut + 3);

    // select this env's delta via shuffle (no dependent load)
    const int dy = __shfl_sync(0xffffffffu, dval, 2 * a);
    const int dx = __shfl_sync(0xffffffffu, dval, 2 * a + 1);

    const int nyc = min(max(y0 + dy, 0), HW - 1);   // candidate move pos
    const int nxc = min(max(x0 + dx, 0), HW - 1);

    // ---- ROUND 2: gather BOTH candidate windows (8 parallel loads/lane) ----
    float wm[4], ws[4];
    #pragma unroll
    for (int j = 0; j < 4; j++) {
        const int c  = lane + 32 * j;           // cell index 0..127
        const int wy = c / VIEW - RAD;
        const int wx = c % VIEW - RAD;

        // move-window
        {
            const int gy = nyc + wy, gx = nxc + wx;
            float v = 1.0f;
            if (c < CELLS && (unsigned)gy < (unsigned)HW && (unsigned)gx < (unsigned)HW)
                v = __ldg(g + gy * HW + gx);
            wm[j] = v;
        }
        // stay-window
        {
            const int gy = y0 + wy, gx = x0 + wx;
            float v = 1.0f;
            if (c < CELLS && (unsigned)gy < (unsigned)HW && (unsigned)gx < (unsigned)HW)
                v = __ldg(g + gy * HW + gx);
            ws[j] = v;
        }
    }

    // window centers: cell c=60 -> lane 28, j=1. Center is always in-bounds.
    const float tgt   = __shfl_sync(0xffffffffu, wm[1], 28);
    const float stayc = __shfl_sync(0xffffffffu, ws[1], 28);

    const bool  blocked  = (tgt == 1.0f);
    const float cell     = blocked ? stayc : tgt;
    const bool  food     = (cell == 2.0f);
    const bool  poison   = (cell == 3.0f);
    const bool  consumed = food | poison;
    const float reward   = (food ? 10.0f : 0.0f) - (poison ? 10.0f : 0.0f);
    const float energy   = en0 - 1.0f + reward;

    float* __restrict__ o = out + (size_t)env * OBS_PER_ENV;
    #pragma unroll
    for (int j = 0; j < 4; j++) {
        const int c = lane + 32 * j;
        if (c < CELLS) {
            float v = blocked ? ws[j] : wm[j];
            if (consumed && c == 60) v = 0.0f;   // landed cell becomes EMPTY
            const int   vi = (int)v;
            const float lv = (vi == 0) ? l0 : (vi == 1) ? l1 : (vi == 2) ? l2 : l3;
            o[0 * CELLS + c] = (v == 2.0f) ? 1.0f : 0.0f;
            o[1 * CELLS + c] = (v == 3.0f) ? 1.0f : 0.0f;
            o[2 * CELLS + c] = (v == 1.0f) ? 1.0f : 0.0f;
            o[3 * CELLS + c] = lv;
            o[4 * CELLS + c] = v;
            o[5 * CELLS + c] = energy;
        }
    }
}

extern "C" void kernel_launch(void* const* d_in, const int* in_sizes, int n_in,
                              void* d_out, int out_size)
{
    const float* grids   = (const float*)d_in[0];
    const float* energy  = (const float*)d_in[1];
    const float* lut     = (const float*)d_in[2];
    const int*   ax      = (const int*)  d_in[3];
    const int*   ay      = (const int*)  d_in[4];
    // d_in[5] agent_steps unused
    const int*   actions = (const int*)  d_in[6];
    const int*   deltas  = (const int*)  d_in[7];
    float*       out     = (float*)      d_out;

    const int n_envs = in_sizes[1];
    const int blocks = (n_envs + ENVS_PER_BLOCK - 1) / ENVS_PER_BLOCK;

    env_step_kernel<<<blocks, 256>>>(grids, energy, lut, ax, ay, actions, deltas, out, n_envs);
}

// round 5
// speedup vs baseline: 1.1701x; 1.0209x over previous
#include <cuda_runtime.h>
#include <cuda_bf16.h>

// Gridworld env step: warp-per-2-envs, fully interleaved chains.
// Single wave (512 CTAs), 16 independent gather loads in flight per thread.
//
// Inputs (metadata order):
//   0 grids (N,64,64) f32 | 1 energy (N,) f32 | 2 lut (5,) f32
//   3 agent_x (N,) i32 | 4 agent_y (N,) i32 | 5 agent_steps (unused)
//   6 actions (N,) i32 | 7 action_deltas (9,2) i32
// Output: obs (N, 6, 11, 11) f32

#define HW   64
#define VIEW 11
#define RAD  5
#define CELLS 121            // 11*11
#define OBS_PER_ENV 726      // 6*121
#define WARPS_PER_BLOCK 8
#define ENVS_PER_WARP 2
#define ENVS_PER_BLOCK (WARPS_PER_BLOCK * ENVS_PER_WARP)  // 16

__global__ __launch_bounds__(256)
void env_step_kernel(const float* __restrict__ grids,
                     const float* __restrict__ energy_in,
                     const float* __restrict__ lut,
                     const int*   __restrict__ agent_x,
                     const int*   __restrict__ agent_y,
                     const int*   __restrict__ actions,
                     const int*   __restrict__ deltas,
                     float*       __restrict__ out,
                     int n_envs)
{
    const int warp = (blockIdx.x * WARPS_PER_BLOCK) + (threadIdx.x >> 5);
    const int lane = threadIdx.x & 31;
    const int env0 = warp * ENVS_PER_WARP;
    if (env0 >= n_envs) return;

    // ---- ROUND 1: every independent load for BOTH envs, plus shared tables ----
    const int dval = (lane < 18) ? __ldg(deltas + lane) : 0;   // whole delta table
    const float l0 = __ldg(lut + 0);
    const float l1 = __ldg(lut + 1);
    const float l2 = __ldg(lut + 2);
    const float l3 = __ldg(lut + 3);

    int   a[2], y0[2], x0[2];
    float en[2];
    #pragma unroll
    for (int e = 0; e < 2; e++) {
        a[e]  = __ldg(actions   + env0 + e);
        y0[e] = __ldg(agent_y   + env0 + e);
        x0[e] = __ldg(agent_x   + env0 + e);
        en[e] = __ldg(energy_in + env0 + e);
    }

    int nyc[2], nxc[2];
    #pragma unroll
    for (int e = 0; e < 2; e++) {
        const int dy = __shfl_sync(0xffffffffu, dval, 2 * a[e]);
        const int dx = __shfl_sync(0xffffffffu, dval, 2 * a[e] + 1);
        nyc[e] = min(max(y0[e] + dy, 0), HW - 1);
        nxc[e] = min(max(x0[e] + dx, 0), HW - 1);
    }

    // ---- ROUND 2: gather both candidate windows for both envs (16 loads) ----
    float wm[2][4], ws[2][4];
    #pragma unroll
    for (int j = 0; j < 4; j++) {
        const int c  = lane + 32 * j;        // cell 0..127
        const int wy = c / VIEW - RAD;
        const int wx = c % VIEW - RAD;
        #pragma unroll
        for (int e = 0; e < 2; e++) {
            const float* __restrict__ g = grids + (size_t)(env0 + e) * (HW * HW);
            {   // move-window
                const int gy = nyc[e] + wy, gx = nxc[e] + wx;
                float v = 1.0f;
                if (c < CELLS && (unsigned)gy < (unsigned)HW && (unsigned)gx < (unsigned)HW)
                    v = __ldg(g + gy * HW + gx);
                wm[e][j] = v;
            }
            {   // stay-window
                const int gy = y0[e] + wy, gx = x0[e] + wx;
                float v = 1.0f;
                if (c < CELLS && (unsigned)gy < (unsigned)HW && (unsigned)gx < (unsigned)HW)
                    v = __ldg(g + gy * HW + gx);
                ws[e][j] = v;
            }
        }
    }

    // ---- resolve + emit, per env ----
    #pragma unroll
    for (int e = 0; e < 2; e++) {
        // center cell c=60 lives in lane 28, j=1; always in-bounds
        const float tgt   = __shfl_sync(0xffffffffu, wm[e][1], 28);
        const float stayc = __shfl_sync(0xffffffffu, ws[e][1], 28);

        const bool  blocked  = (tgt == 1.0f);
        const float cell     = blocked ? stayc : tgt;
        const bool  food     = (cell == 2.0f);
        const bool  poison   = (cell == 3.0f);
        const bool  consumed = food | poison;
        const float reward   = (food ? 10.0f : 0.0f) - (poison ? 10.0f : 0.0f);
        const float energy   = en[e] - 1.0f + reward;

        float* __restrict__ o = out + (size_t)(env0 + e) * OBS_PER_ENV;
        #pragma unroll
        for (int j = 0; j < 4; j++) {
            const int c = lane + 32 * j;
            if (c < CELLS) {
                float v = blocked ? ws[e][j] : wm[e][j];
                if (consumed && c == 60) v = 0.0f;    // landed cell -> EMPTY
                const int   vi = (int)v;
                const float lv = (vi == 0) ? l0 : (vi == 1) ? l1 : (vi == 2) ? l2 : l3;
                o[0 * CELLS + c] = (v == 2.0f) ? 1.0f : 0.0f;
                o[1 * CELLS + c] = (v == 3.0f) ? 1.0f : 0.0f;
                o[2 * CELLS + c] = (v == 1.0f) ? 1.0f : 0.0f;
                o[3 * CELLS + c] = lv;
                o[4 * CELLS + c] = v;
                o[5 * CELLS + c] = energy;
            }
        }
    }
}

extern "C" void kernel_launch(void* const* d_in, const int* in_sizes, int n_in,
                              void* d_out, int out_size)
{
    const float* grids   = (const float*)d_in[0];
    const float* energy  = (const float*)d_in[1];
    const float* lut     = (const float*)d_in[2];
    const int*   ax      = (const int*)  d_in[3];
    const int*   ay      = (const int*)  d_in[4];
    // d_in[5] agent_steps unused
    const int*   actions = (const int*)  d_in[6];
    const int*   deltas  = (const int*)  d_in[7];
    float*       out     = (float*)      d_out;

    const int n_envs = in_sizes[1];
    const int blocks = (n_envs + ENVS_PER_BLOCK - 1) / ENVS_PER_BLOCK;

    env_step_kernel<<<blocks, 256>>>(grids, energy, lut, ax, ay, actions, deltas, out, n_envs);
}